// round 1
// baseline (speedup 1.0000x reference)
#include <cuda_runtime.h>

#define BZ 2
#define NN 512
#define CI 16
#define CO 16
#define HH 64

#define ATILE  32
#define BGRP   4
#define BSPLIT 16
#define BCHUNK (NN / BSPLIT)     // 32 b's per CTA
#define NITER  (BCHUNK / BGRP)   // 8 iterations of 4 b's
#define GSTR   (CO * HH + 8)     // 1032 floats: pad so bb-stride != 0 mod 32 banks

// Scratch (no allocation allowed; device globals are the sanctioned path)
__device__ float g_G[BZ * NN * CO * HH];   // [z][b][i][h]  (4 MB)
__device__ float g_B2[BZ * NN * CO];       // [z][b][i]

// gelu (tanh approximation, matching jax.nn.gelu approximate=True):
//   gelu(x) = x * sigmoid(1.5957691216*(x + 0.044715 x^3))
__device__ __forceinline__ float gelu_fast(float x) {
    const float K = -(2.0f * 0.7978845608028654f * 1.4426950408889634f); // -2*sqrt(2/pi)*log2(e)
    float x2 = x * x;
    float p  = x * fmaf(0.044715f, x2, 1.0f) * K;   // exponent in log2 domain
    float e;  asm("ex2.approx.f32 %0, %1;" : "=f"(e) : "f"(p));
    float d = 1.0f + e;
    float r;  asm("rcp.approx.f32 %0, %1;" : "=f"(r) : "f"(d));
    return x * r;
}

// ---------------------------------------------------------------------------
// Kernel 1: G[z,b,i,h] = sum_j W2[i*16+j,h] * f[z,b,j];  Bias2[z,b,i] likewise.
// grid = 1024 (one block per (z,b)), 256 threads: thread -> (i, h-quad)
// ---------------------------------------------------------------------------
__global__ void precompute_G(const float* __restrict__ features,
                             const float* __restrict__ W2,
                             const float* __restrict__ b2)
{
    __shared__ float fs[CI];
    const int zb = blockIdx.x;
    const int t  = threadIdx.x;
    if (t < CI) fs[t] = features[zb * CI + t];
    __syncthreads();

    const int i = t >> 4, hq = t & 15;
    float4 acc = make_float4(0.f, 0.f, 0.f, 0.f);
#pragma unroll
    for (int j = 0; j < CI; j++) {
        const float4 w = reinterpret_cast<const float4*>(W2)[(i * CI + j) * (HH / 4) + hq];
        const float f = fs[j];
        acc.x = fmaf(f, w.x, acc.x);
        acc.y = fmaf(f, w.y, acc.y);
        acc.z = fmaf(f, w.z, acc.z);
        acc.w = fmaf(f, w.w, acc.w);
    }
    reinterpret_cast<float4*>(g_G)[(zb * CO + i) * (HH / 4) + hq] = acc;

    if (t < CO) {
        float s = 0.f;
#pragma unroll
        for (int j = 0; j < CI; j++) s = fmaf(b2[t * CI + j], fs[j], s);
        g_B2[zb * CO + t] = s;
    }
}

// ---------------------------------------------------------------------------
// Kernel 2: out[z,a,b,i] = sum_h gelu(MLP1(geom_b - geom_a))[h] * G[z,b,i,h] + Bias2
// 128 threads: thread = (a_local = t>>2, bb = t&3). h kept in registers.
// G tile (4 b's, 16 KB) double-buffered via cp.async.
// ---------------------------------------------------------------------------
__global__ __launch_bounds__(128) void ApplyKernel_main(
    const float* __restrict__ geom,
    const float* __restrict__ W1,
    const float* __restrict__ b1,
    float* __restrict__ out)
{
    __shared__ float4 W1s[HH];
    __shared__ float  b1s[HH];
    __shared__ __align__(16) float Gs[2][BGRP * GSTR];

    const int t  = threadIdx.x;
    const int z  = blockIdx.z;
    const int a  = blockIdx.y * ATILE + (t >> 2);
    const int bb = t & 3;
    const int b0 = blockIdx.x * BCHUNK;

    if (t < HH) {
        W1s[t] = reinterpret_cast<const float4*>(W1)[t];
        b1s[t] = b1[t];
    }

    const float gax = geom[(z * NN + a) * 3 + 0];
    const float gay = geom[(z * NN + a) * 3 + 1];
    const float gaz = geom[(z * NN + a) * 3 + 2];

    // prologue: stage G for group 0 into buffer 0
    {
        const float* src = &g_G[(size_t)(z * NN + b0) * CO * HH];
#pragma unroll
        for (int k = 0; k < 8; k++) {
            int q = t + k * 128;            // 1024 float4 quads = 16 KB
            int qb = q >> 8;                // which b of the group
            int rem = q & 255;              // quad within that b
            unsigned dst = (unsigned)__cvta_generic_to_shared(&Gs[0][qb * GSTR + rem * 4]);
            asm volatile("cp.async.ca.shared.global [%0], [%1], 16;"
                         :: "r"(dst), "l"(src + qb * CO * HH + rem * 4));
        }
        asm volatile("cp.async.commit_group;");
    }

    for (int it = 0; it < NITER; it++) {
        float* gbuf = Gs[it & 1];
        if (it + 1 < NITER) {
            const float* src = &g_G[(size_t)(z * NN + b0 + (it + 1) * BGRP) * CO * HH];
            float* dbuf = Gs[(it + 1) & 1];
#pragma unroll
            for (int k = 0; k < 8; k++) {
                int q = t + k * 128;
                int qb = q >> 8;
                int rem = q & 255;
                unsigned dst = (unsigned)__cvta_generic_to_shared(&dbuf[qb * GSTR + rem * 4]);
                asm volatile("cp.async.ca.shared.global [%0], [%1], 16;"
                             :: "r"(dst), "l"(src + qb * CO * HH + rem * 4));
            }
            asm volatile("cp.async.commit_group;");
            asm volatile("cp.async.wait_group 1;");
        } else {
            asm volatile("cp.async.wait_group 0;");
        }
        __syncthreads();   // buffer(it) ready; also publishes W1s on iter 0

        const int b = b0 + it * BGRP + bb;
        const float gbx = __ldg(&geom[(z * NN + b) * 3 + 0]);
        const float gby = __ldg(&geom[(z * NN + b) * 3 + 1]);
        const float gbz = __ldg(&geom[(z * NN + b) * 3 + 2]);
        const float dx = gbx - gax, dy = gby - gay, dzv = gbz - gaz;
        const float r2  = fmaf(dx, dx, fmaf(dy, dy, dzv * dzv));
        const float nrm = sqrtf(r2 + 1e-12f);

        float acc[CO];
        {
            const float4* bp = reinterpret_cast<const float4*>(&g_B2[(z * NN + b) * CO]);
#pragma unroll
            for (int iq = 0; iq < 4; iq++) {
                float4 v = __ldg(&bp[iq]);
                acc[iq * 4 + 0] = v.x; acc[iq * 4 + 1] = v.y;
                acc[iq * 4 + 2] = v.z; acc[iq * 4 + 3] = v.w;
            }
        }

        const float* gsb = &gbuf[bb * GSTR];
#pragma unroll
        for (int half = 0; half < 2; half++) {
            float4 hreg[8];
#pragma unroll
            for (int hq = 0; hq < 8; hq++) {
                float hv[4];
#pragma unroll
                for (int c = 0; c < 4; c++) {
                    int h = half * 32 + hq * 4 + c;
                    float4 w = W1s[h];
                    float x = fmaf(dx, w.x, fmaf(dy, w.y,
                              fmaf(dzv, w.z, fmaf(nrm, w.w, b1s[h]))));
                    hv[c] = gelu_fast(x);
                }
                hreg[hq] = make_float4(hv[0], hv[1], hv[2], hv[3]);
            }
#pragma unroll
            for (int hq = 0; hq < 8; hq++) {
                const float4 hvv = hreg[hq];
#pragma unroll
                for (int i = 0; i < CO; i++) {
                    const float4 g = *reinterpret_cast<const float4*>(
                        &gsb[i * HH + half * 32 + hq * 4]);
                    acc[i] = fmaf(hvv.x, g.x, fmaf(hvv.y, g.y,
                             fmaf(hvv.z, g.z, fmaf(hvv.w, g.w, acc[i]))));
                }
            }
        }

        float* op = &out[((z * NN + a) * NN + b) * CO];
#pragma unroll
        for (int iq = 0; iq < 4; iq++) {
            reinterpret_cast<float4*>(op)[iq] =
                make_float4(acc[iq * 4 + 0], acc[iq * 4 + 1],
                            acc[iq * 4 + 2], acc[iq * 4 + 3]);
        }
        __syncthreads();   // all lanes done reading gbuf before it is re-filled
    }
}

extern "C" void kernel_launch(void* const* d_in, const int* in_sizes, int n_in,
                              void* d_out, int out_size) {
    const float* features = (const float*)d_in[0];
    const float* geometry = (const float*)d_in[1];
    const float* W1       = (const float*)d_in[2];
    const float* b1       = (const float*)d_in[3];
    const float* W2       = (const float*)d_in[4];
    const float* b2       = (const float*)d_in[5];
    float* out = (float*)d_out;

    precompute_G<<<BZ * NN, 256>>>(features, W2, b2);

    dim3 grid(BSPLIT, NN / ATILE, BZ);
    ApplyKernel_main<<<grid, 128>>>(geometry, W1, b1, out);
}

// round 4
// speedup vs baseline: 1.1114x; 1.1114x over previous
#include <cuda_runtime.h>

#define BZ 2
#define NN 512
#define CI 16
#define CO 16
#define HH 64

#define ATILE  32
#define BGRP   4
#define BSPLIT 32
#define BCHUNK (NN / BSPLIT)     // 16 b's per CTA
#define NITER  (BCHUNK / BGRP)   // 4 iterations of 4 b's
// per-b smem slot: 1024 G floats + 16 B2 floats + 8 pad.
// stride 1048*4=4192 B, mod 128 = 96 -> bb offsets hit distinct bank groups.
#define GSTR   1048

__device__ float g_G[BZ * NN * CO * HH];   // [z][b][i][h]  (4 MB)
__device__ float g_B2[BZ * NN * CO];       // [z][b][i]

// gelu (tanh approximation == jax.nn.gelu default):
//   gelu(x) = x * sigmoid(2*sqrt(2/pi)*(x + 0.044715 x^3))
__device__ __forceinline__ float gelu_fast(float x) {
    const float K = -(2.0f * 0.7978845608028654f * 1.4426950408889634f); // -2*sqrt(2/pi)*log2(e)
    float x2 = x * x;
    float p  = x * fmaf(0.044715f, x2, 1.0f) * K;   // exponent in log2 domain
    float e;  asm("ex2.approx.f32 %0, %1;" : "=f"(e) : "f"(p));
    float d = 1.0f + e;
    float r;  asm("rcp.approx.f32 %0, %1;" : "=f"(r) : "f"(d));
    return x * r;
}

// ---------------------------------------------------------------------------
// Kernel 1: G[z,b,i,h] = sum_j W2[i*16+j,h] * f[z,b,j];  B2[z,b,i] likewise.
// ---------------------------------------------------------------------------
__global__ void precompute_G(const float* __restrict__ features,
                             const float* __restrict__ W2,
                             const float* __restrict__ b2)
{
    __shared__ float fs[CI];
    const int zb = blockIdx.x;
    const int t  = threadIdx.x;
    if (t < CI) fs[t] = features[zb * CI + t];
    __syncthreads();

    const int i = t >> 4, hq = t & 15;
    float4 acc = make_float4(0.f, 0.f, 0.f, 0.f);
#pragma unroll
    for (int j = 0; j < CI; j++) {
        const float4 w = reinterpret_cast<const float4*>(W2)[(i * CI + j) * (HH / 4) + hq];
        const float f = fs[j];
        acc.x = fmaf(f, w.x, acc.x);
        acc.y = fmaf(f, w.y, acc.y);
        acc.z = fmaf(f, w.z, acc.z);
        acc.w = fmaf(f, w.w, acc.w);
    }
    reinterpret_cast<float4*>(g_G)[(zb * CO + i) * (HH / 4) + hq] = acc;

    if (t < CO) {
        float s = 0.f;
#pragma unroll
        for (int j = 0; j < CI; j++) s = fmaf(b2[t * CI + j], fs[j], s);
        g_B2[zb * CO + t] = s;
    }
}

// ---------------------------------------------------------------------------
// Kernel 2: out[z,a,b,i] = sum_h gelu(MLP1(geom_b - geom_a))[h] * G[z,b,i,h] + B2
// 128 threads: thread = (a_local = t>>2, bb = t&3). h computed in registers,
// contracted immediately per h-quad (no hreg buffer -> low regs, high occ).
// G+B2 tile (4 b's, ~16.8 KB) double-buffered via cp.async.
// ---------------------------------------------------------------------------
__global__ __launch_bounds__(128, 6) void ApplyKernel_main(
    const float* __restrict__ geom,
    const float* __restrict__ W1,
    const float* __restrict__ b1,
    float* __restrict__ out)
{
    __shared__ float4 W1s[HH];
    __shared__ float  b1s[HH];
    __shared__ __align__(16) float Gs[2][BGRP * GSTR];

    const int t  = threadIdx.x;
    const int z  = blockIdx.z;
    const int a  = blockIdx.y * ATILE + (t >> 2);
    const int bb = t & 3;
    const int b0 = blockIdx.x * BCHUNK;

    if (t < HH) {
        W1s[t] = reinterpret_cast<const float4*>(W1)[t];
        b1s[t] = b1[t];
    }

    const float gax = geom[(z * NN + a) * 3 + 0];
    const float gay = geom[(z * NN + a) * 3 + 1];
    const float gaz = geom[(z * NN + a) * 3 + 2];

    // stage group 'grp' (4 b's of G + B2) into buffer 'buf'
    auto stage = [&](int grp, int buf) {
        const int bbase = b0 + grp * BGRP;
        const float* src = &g_G[(size_t)(z * NN + bbase) * CO * HH];
#pragma unroll
        for (int k = 0; k < 8; k++) {
            int q = t + k * 128;            // 1024 float4 quads of G
            int qb = q >> 8;
            int rem = q & 255;
            unsigned dst = (unsigned)__cvta_generic_to_shared(&Gs[buf][qb * GSTR + rem * 4]);
            asm volatile("cp.async.ca.shared.global [%0], [%1], 16;"
                         :: "r"(dst), "l"(src + qb * CO * HH + rem * 4));
        }
        if (t < 16) {                       // 16 float4 quads of B2
            int qb = t >> 2, iq = t & 3;
            const float* bsrc = &g_B2[(size_t)(z * NN + bbase + qb) * CO + iq * 4];
            unsigned dst = (unsigned)__cvta_generic_to_shared(
                &Gs[buf][qb * GSTR + CO * HH + iq * 4]);
            asm volatile("cp.async.ca.shared.global [%0], [%1], 16;"
                         :: "r"(dst), "l"(bsrc));
        }
        asm volatile("cp.async.commit_group;");
    };

    stage(0, 0);

    for (int it = 0; it < NITER; it++) {
        float* gbuf = Gs[it & 1];
        if (it + 1 < NITER) {
            stage(it + 1, (it + 1) & 1);
            asm volatile("cp.async.wait_group 1;");
        } else {
            asm volatile("cp.async.wait_group 0;");
        }
        __syncthreads();   // buffer(it) ready; also publishes W1s on iter 0

        const int b = b0 + it * BGRP + bb;
        const float gbx = __ldg(&geom[(z * NN + b) * 3 + 0]);
        const float gby = __ldg(&geom[(z * NN + b) * 3 + 1]);
        const float gbz = __ldg(&geom[(z * NN + b) * 3 + 2]);
        const float dx = gbx - gax, dy = gby - gay, dzv = gbz - gaz;
        const float r2  = fmaf(dx, dx, fmaf(dy, dy, dzv * dzv)) + 1e-12f;
        float nrm; asm("sqrt.approx.f32 %0, %1;" : "=f"(nrm) : "f"(r2));

        const float* gsb = &gbuf[bb * GSTR];

        float acc[CO];
#pragma unroll
        for (int iq = 0; iq < 4; iq++) {
            const float4 v = *reinterpret_cast<const float4*>(&gsb[CO * HH + iq * 4]);
            acc[iq * 4 + 0] = v.x; acc[iq * 4 + 1] = v.y;
            acc[iq * 4 + 2] = v.z; acc[iq * 4 + 3] = v.w;
        }

#pragma unroll
        for (int hq = 0; hq < 16; hq++) {
            float hv[4];
#pragma unroll
            for (int c = 0; c < 4; c++) {
                const int h = hq * 4 + c;
                const float4 w = W1s[h];
                const float x = fmaf(dx, w.x, fmaf(dy, w.y,
                                fmaf(dzv, w.z, fmaf(nrm, w.w, b1s[h]))));
                hv[c] = gelu_fast(x);
            }
#pragma unroll
            for (int i = 0; i < CO; i++) {
                const float4 g = *reinterpret_cast<const float4*>(&gsb[i * HH + hq * 4]);
                acc[i] = fmaf(hv[0], g.x, fmaf(hv[1], g.y,
                         fmaf(hv[2], g.z, fmaf(hv[3], g.w, acc[i]))));
            }
        }

        float* op = &out[((size_t)(z * NN + a) * NN + b) * CO];
#pragma unroll
        for (int iq = 0; iq < 4; iq++) {
            reinterpret_cast<float4*>(op)[iq] =
                make_float4(acc[iq * 4 + 0], acc[iq * 4 + 1],
                            acc[iq * 4 + 2], acc[iq * 4 + 3]);
        }
        __syncthreads();   // all lanes done reading gbuf before refill
    }
}

extern "C" void kernel_launch(void* const* d_in, const int* in_sizes, int n_in,
                              void* d_out, int out_size) {
    const float* features = (const float*)d_in[0];
    const float* geometry = (const float*)d_in[1];
    const float* W1       = (const float*)d_in[2];
    const float* b1       = (const float*)d_in[3];
    const float* W2       = (const float*)d_in[4];
    const float* b2       = (const float*)d_in[5];
    float* out = (float*)d_out;

    precompute_G<<<BZ * NN, 256>>>(features, W2, b2);

    dim3 grid(BSPLIT, NN / ATILE, BZ);
    ApplyKernel_main<<<grid, 128>>>(geometry, W1, b1, out);
}

// round 5
// speedup vs baseline: 1.2846x; 1.1559x over previous
#include <cuda_runtime.h>

#define BZ 2
#define NN 512
#define CI 16
#define CO 16
#define HH 64

#define ATILE  64                // a's per CTA; each thread owns 2 a's (a, a+32)
#define BGRP   4
#define BSPLIT 64
#define BCHUNK (NN / BSPLIT)     // 8 b's per CTA
#define NITER  (BCHUNK / BGRP)   // 2 iterations of 4 b's
// per-b smem slot: 1024 G floats + 16 B2 floats + 8 pad.
// stride 1048*4=4192 B, mod 128 = 96 -> bb offsets hit distinct bank quadrants.
#define GSTR   1048

__device__ float g_G[BZ * NN * CO * HH];   // [z][b][i][h]  (4 MB)
__device__ float g_B2[BZ * NN * CO];       // [z][b][i]

// gelu (tanh approximation == jax.nn.gelu default):
//   gelu(x) = x * sigmoid(2*sqrt(2/pi)*(x + 0.044715 x^3))
__device__ __forceinline__ float gelu_fast(float x) {
    const float K = -(2.0f * 0.7978845608028654f * 1.4426950408889634f); // -2*sqrt(2/pi)*log2(e)
    float x2 = x * x;
    float p  = x * fmaf(0.044715f, x2, 1.0f) * K;   // exponent in log2 domain
    float e;  asm("ex2.approx.f32 %0, %1;" : "=f"(e) : "f"(p));
    float d = 1.0f + e;
    float r;  asm("rcp.approx.f32 %0, %1;" : "=f"(r) : "f"(d));
    return x * r;
}

// ---------------------------------------------------------------------------
// Kernel 1: G[z,b,i,h] = sum_j W2[i*16+j,h] * f[z,b,j];  B2[z,b,i] likewise.
// ---------------------------------------------------------------------------
__global__ void precompute_G(const float* __restrict__ features,
                             const float* __restrict__ W2,
                             const float* __restrict__ b2)
{
    __shared__ float fs[CI];
    const int zb = blockIdx.x;
    const int t  = threadIdx.x;
    if (t < CI) fs[t] = features[zb * CI + t];
    __syncthreads();

    const int i = t >> 4, hq = t & 15;
    float4 acc = make_float4(0.f, 0.f, 0.f, 0.f);
#pragma unroll
    for (int j = 0; j < CI; j++) {
        const float4 w = reinterpret_cast<const float4*>(W2)[(i * CI + j) * (HH / 4) + hq];
        const float f = fs[j];
        acc.x = fmaf(f, w.x, acc.x);
        acc.y = fmaf(f, w.y, acc.y);
        acc.z = fmaf(f, w.z, acc.z);
        acc.w = fmaf(f, w.w, acc.w);
    }
    reinterpret_cast<float4*>(g_G)[(zb * CO + i) * (HH / 4) + hq] = acc;

    if (t < CO) {
        float s = 0.f;
#pragma unroll
        for (int j = 0; j < CI; j++) s = fmaf(b2[t * CI + j], fs[j], s);
        g_B2[zb * CO + t] = s;
    }
}

// ---------------------------------------------------------------------------
// Kernel 2: out[z,a,b,i] = sum_h gelu(MLP1(geom_b - geom_a))[h] * G[z,b,i,h] + B2
// 128 threads: thread = (a_local = t>>2 owning a and a+32, bb = t&3).
// Each G LDS.128 feeds BOTH a's (8 FMA per 16B shared read) -> LDS-bound fix.
// G+B2 tile (4 b's, ~16.8 KB) double-buffered via cp.async.
// ---------------------------------------------------------------------------
__global__ __launch_bounds__(128, 5) void ApplyKernel_main(
    const float* __restrict__ geom,
    const float* __restrict__ W1,
    const float* __restrict__ b1,
    float* __restrict__ out)
{
    __shared__ float4 W1s[HH];
    __shared__ float  b1s[HH];
    __shared__ __align__(16) float Gs[2][BGRP * GSTR];

    const int t  = threadIdx.x;
    const int z  = blockIdx.z;
    const int a0 = blockIdx.y * ATILE + (t >> 2);   // first a
    const int a1 = a0 + 32;                         // second a
    const int bb = t & 3;
    const int b0 = blockIdx.x * BCHUNK;

    if (t < HH) {
        W1s[t] = reinterpret_cast<const float4*>(W1)[t];
        b1s[t] = b1[t];
    }

    const float ga0x = geom[(z * NN + a0) * 3 + 0];
    const float ga0y = geom[(z * NN + a0) * 3 + 1];
    const float ga0z = geom[(z * NN + a0) * 3 + 2];
    const float ga1x = geom[(z * NN + a1) * 3 + 0];
    const float ga1y = geom[(z * NN + a1) * 3 + 1];
    const float ga1z = geom[(z * NN + a1) * 3 + 2];

    // stage group 'grp' (4 b's of G + B2) into buffer 'buf'
    auto stage = [&](int grp, int buf) {
        const int bbase = b0 + grp * BGRP;
        const float* src = &g_G[(size_t)(z * NN + bbase) * CO * HH];
#pragma unroll
        for (int k = 0; k < 8; k++) {
            int q = t + k * 128;            // 1024 float4 quads of G
            int qb = q >> 8;
            int rem = q & 255;
            unsigned dst = (unsigned)__cvta_generic_to_shared(&Gs[buf][qb * GSTR + rem * 4]);
            asm volatile("cp.async.ca.shared.global [%0], [%1], 16;"
                         :: "r"(dst), "l"(src + qb * CO * HH + rem * 4));
        }
        if (t < 16) {                       // 16 float4 quads of B2
            int qb = t >> 2, iq = t & 3;
            const float* bsrc = &g_B2[(size_t)(z * NN + bbase + qb) * CO + iq * 4];
            unsigned dst = (unsigned)__cvta_generic_to_shared(
                &Gs[buf][qb * GSTR + CO * HH + iq * 4]);
            asm volatile("cp.async.ca.shared.global [%0], [%1], 16;"
                         :: "r"(dst), "l"(bsrc));
        }
        asm volatile("cp.async.commit_group;");
    };

    stage(0, 0);

    for (int it = 0; it < NITER; it++) {
        float* gbuf = Gs[it & 1];
        if (it + 1 < NITER) {
            stage(it + 1, (it + 1) & 1);
            asm volatile("cp.async.wait_group 1;");
        } else {
            asm volatile("cp.async.wait_group 0;");
        }
        __syncthreads();   // buffer(it) ready; also publishes W1s on iter 0

        const int b = b0 + it * BGRP + bb;
        const float gbx = __ldg(&geom[(z * NN + b) * 3 + 0]);
        const float gby = __ldg(&geom[(z * NN + b) * 3 + 1]);
        const float gbz = __ldg(&geom[(z * NN + b) * 3 + 2]);

        const float dx0 = gbx - ga0x, dy0 = gby - ga0y, dz0 = gbz - ga0z;
        const float dx1 = gbx - ga1x, dy1 = gby - ga1y, dz1 = gbz - ga1z;
        const float r20 = fmaf(dx0, dx0, fmaf(dy0, dy0, dz0 * dz0)) + 1e-12f;
        const float r21 = fmaf(dx1, dx1, fmaf(dy1, dy1, dz1 * dz1)) + 1e-12f;
        float nrm0; asm("sqrt.approx.f32 %0, %1;" : "=f"(nrm0) : "f"(r20));
        float nrm1; asm("sqrt.approx.f32 %0, %1;" : "=f"(nrm1) : "f"(r21));

        const float* gsb = &gbuf[bb * GSTR];

        float acc0[CO], acc1[CO];
#pragma unroll
        for (int iq = 0; iq < 4; iq++) {
            const float4 v = *reinterpret_cast<const float4*>(&gsb[CO * HH + iq * 4]);
            acc0[iq * 4 + 0] = v.x; acc0[iq * 4 + 1] = v.y;
            acc0[iq * 4 + 2] = v.z; acc0[iq * 4 + 3] = v.w;
            acc1[iq * 4 + 0] = v.x; acc1[iq * 4 + 1] = v.y;
            acc1[iq * 4 + 2] = v.z; acc1[iq * 4 + 3] = v.w;
        }

#pragma unroll
        for (int hq = 0; hq < 16; hq++) {
            float hv0[4], hv1[4];
#pragma unroll
            for (int c = 0; c < 4; c++) {
                const int h = hq * 4 + c;
                const float4 w = W1s[h];
                const float bw = b1s[h];
                const float x0 = fmaf(dx0, w.x, fmaf(dy0, w.y,
                                 fmaf(dz0, w.z, fmaf(nrm0, w.w, bw))));
                const float x1 = fmaf(dx1, w.x, fmaf(dy1, w.y,
                                 fmaf(dz1, w.z, fmaf(nrm1, w.w, bw))));
                hv0[c] = gelu_fast(x0);
                hv1[c] = gelu_fast(x1);
            }
#pragma unroll
            for (int i = 0; i < CO; i++) {
                const float4 g = *reinterpret_cast<const float4*>(&gsb[i * HH + hq * 4]);
                acc0[i] = fmaf(hv0[0], g.x, fmaf(hv0[1], g.y,
                          fmaf(hv0[2], g.z, fmaf(hv0[3], g.w, acc0[i]))));
                acc1[i] = fmaf(hv1[0], g.x, fmaf(hv1[1], g.y,
                          fmaf(hv1[2], g.z, fmaf(hv1[3], g.w, acc1[i]))));
            }
        }

        float* op0 = &out[((size_t)(z * NN + a0) * NN + b) * CO];
        float* op1 = &out[((size_t)(z * NN + a1) * NN + b) * CO];
#pragma unroll
        for (int iq = 0; iq < 4; iq++) {
            reinterpret_cast<float4*>(op0)[iq] =
                make_float4(acc0[iq * 4 + 0], acc0[iq * 4 + 1],
                            acc0[iq * 4 + 2], acc0[iq * 4 + 3]);
            reinterpret_cast<float4*>(op1)[iq] =
                make_float4(acc1[iq * 4 + 0], acc1[iq * 4 + 1],
                            acc1[iq * 4 + 2], acc1[iq * 4 + 3]);
        }
        __syncthreads();   // all lanes done reading gbuf before refill
    }
}

extern "C" void kernel_launch(void* const* d_in, const int* in_sizes, int n_in,
                              void* d_out, int out_size) {
    const float* features = (const float*)d_in[0];
    const float* geometry = (const float*)d_in[1];
    const float* W1       = (const float*)d_in[2];
    const float* b1       = (const float*)d_in[3];
    const float* W2       = (const float*)d_in[4];
    const float* b2       = (const float*)d_in[5];
    float* out = (float*)d_out;

    precompute_G<<<BZ * NN, 256>>>(features, W2, b2);

    dim3 grid(BSPLIT, NN / ATILE, BZ);
    ApplyKernel_main<<<grid, 128>>>(geometry, W1, b1, out);
}